// round 5
// baseline (speedup 1.0000x reference)
#include <cuda_runtime.h>

namespace {

constexpr int Bn = 32768;
constexpr int Nn = 512;
constexpr int Fn = 8;
constexpr int On = 32;
constexpr int T  = 512;          // one thread per neighbor
constexpr int NW = T / 32;       // 16 warps

__global__ __launch_bounds__(T, 4)
void gat_kernel(const float* __restrict__ ego,          // [B, F]
                const float* __restrict__ neigh,        // [B, N, F]
                const int*   __restrict__ mask,         // [B, N] int32
                const float* __restrict__ W_ego,        // [F, F]
                const float* __restrict__ b_ego,        // [F]
                const float* __restrict__ w_attn,       // [2F]
                const float* __restrict__ b_attn,       // [1]
                const float* __restrict__ W_out,        // [F, OUT]
                const float* __restrict__ b_out,        // [OUT]
                float* __restrict__ out)                // [B, OUT]
{
    const int b    = blockIdx.x;
    const int t    = threadIdx.x;
    const int warp = t >> 5;
    const int lane = t & 31;

    __shared__ float s_max[NW];
    __shared__ float s_sum[NW];
    __shared__ float s_part[NW][Fn];
    __shared__ float s_tb;
    __shared__ float s_agg[Fn];

    // ---- Front-batched, fully coalesced loads. Thread t owns neighbor row t.
    // Streaming hint: zero reuse, keep L2 for other blocks' lines.
    const float4* np4 = reinterpret_cast<const float4*>(neigh + (size_t)b * (Nn * Fn));
    float4 na = __ldcs(&np4[2 * t]);
    float4 nb = __ldcs(&np4[2 * t + 1]);
    const int m = __ldcs(&mask[(size_t)b * Nn + t]);

    // ---- Per-row ego scalar (tiny, cache-resident): one thread.
    if (t == 0) {
        float tb = b_attn[0];
#pragma unroll
        for (int j = 0; j < Fn; j++) {
            float p = b_ego[j];
#pragma unroll
            for (int i = 0; i < Fn; i++)
                p += ego[(size_t)b * Fn + i] * W_ego[i * Fn + j];
            tb += p * w_attn[j];
        }
        s_tb = tb;
    }
    __syncthreads();
    const float tb = s_tb;

    // ---- Score for my neighbor (wa_n loads hit L1/L2 constants).
    constexpr float NEG = -1e9f;
    float sc = tb
             + na.x * w_attn[Fn + 0] + na.y * w_attn[Fn + 1]
             + na.z * w_attn[Fn + 2] + na.w * w_attn[Fn + 3]
             + nb.x * w_attn[Fn + 4] + nb.y * w_attn[Fn + 5]
             + nb.z * w_attn[Fn + 6] + nb.w * w_attn[Fn + 7];
    sc = m ? sc : NEG;

    // ---- Block max.
    float mx = sc;
#pragma unroll
    for (int o = 16; o; o >>= 1)
        mx = fmaxf(mx, __shfl_xor_sync(0xffffffffu, mx, o));
    if (lane == 0) s_max[warp] = mx;
    __syncthreads();
    mx = s_max[0];
#pragma unroll
    for (int w = 1; w < NW; w++) mx = fmaxf(mx, s_max[w]);

    // ---- exp + block sum (masked lanes contribute exact 0, matching reference).
    const float e = m ? __expf(sc - mx) : 0.f;
    float sum = e;
#pragma unroll
    for (int o = 16; o; o >>= 1)
        sum += __shfl_xor_sync(0xffffffffu, sum, o);
    if (lane == 0) s_sum[warp] = sum;

    // ---- Weighted aggregation: scale my row in place, butterfly-reduce 8 floats.
    na.x *= e; na.y *= e; na.z *= e; na.w *= e;
    nb.x *= e; nb.y *= e; nb.z *= e; nb.w *= e;
#pragma unroll
    for (int o = 16; o; o >>= 1) {
        na.x += __shfl_xor_sync(0xffffffffu, na.x, o);
        na.y += __shfl_xor_sync(0xffffffffu, na.y, o);
        na.z += __shfl_xor_sync(0xffffffffu, na.z, o);
        na.w += __shfl_xor_sync(0xffffffffu, na.w, o);
        nb.x += __shfl_xor_sync(0xffffffffu, nb.x, o);
        nb.y += __shfl_xor_sync(0xffffffffu, nb.y, o);
        nb.z += __shfl_xor_sync(0xffffffffu, nb.z, o);
        nb.w += __shfl_xor_sync(0xffffffffu, nb.w, o);
    }
    if (lane == 0) {
        s_part[warp][0] = na.x; s_part[warp][1] = na.y;
        s_part[warp][2] = na.z; s_part[warp][3] = na.w;
        s_part[warp][4] = nb.x; s_part[warp][5] = nb.y;
        s_part[warp][6] = nb.z; s_part[warp][7] = nb.w;
    }
    __syncthreads();

    // ---- Normalize (all-masked row: tot==0 -> agg=0 -> out=b_out).
    if (t < Fn) {
        float tot = s_sum[0];
#pragma unroll
        for (int w = 1; w < NW; w++) tot += s_sum[w];
        const float rinv = (tot > 0.f) ? (1.f / tot) : 0.f;
        float a = s_part[0][t];
#pragma unroll
        for (int w = 1; w < NW; w++) a += s_part[w][t];
        s_agg[t] = a * rinv;
    }
    __syncthreads();

    // ---- Output GEMV: out[b, o] = agg . W_out[:, o] + b_out[o].
    if (t < On) {
        float v = b_out[t];
#pragma unroll
        for (int f = 0; f < Fn; f++)
            v += s_agg[f] * W_out[f * On + t];
        out[(size_t)b * On + t] = v;
    }
}

} // namespace

extern "C" void kernel_launch(void* const* d_in, const int* in_sizes, int n_in,
                              void* d_out, int out_size)
{
    const float* ego    = (const float*)d_in[0];
    const float* neigh  = (const float*)d_in[1];
    const int*   mask   = (const int*)d_in[2];
    const float* W_ego  = (const float*)d_in[3];
    const float* b_ego  = (const float*)d_in[4];
    const float* w_attn = (const float*)d_in[5];
    const float* b_attn = (const float*)d_in[6];
    const float* W_out  = (const float*)d_in[7];
    const float* b_out  = (const float*)d_in[8];
    float*       out    = (float*)d_out;

    gat_kernel<<<Bn, T>>>(ego, neigh, mask, W_ego, b_ego, w_attn, b_attn,
                          W_out, b_out, out);
}

// round 6
// speedup vs baseline: 1.8840x; 1.8840x over previous
#include <cuda_runtime.h>
#include <cstdint>

namespace {

constexpr int Bn = 32768;
constexpr int Nn = 512;
constexpr int Fn = 8;
constexpr int On = 32;
constexpr int T  = 128;          // threads per block
constexpr int K  = Nn / T;       // 4 neighbors per thread

constexpr unsigned NEIGH_BYTES = Nn * Fn * 4;   // 16384
constexpr unsigned MASK_BYTES  = Nn * 4;        // 2048

__device__ __forceinline__ uint32_t s2u(const void* p) {
    uint32_t a;
    asm("{ .reg .u64 t; cvta.to.shared.u64 t, %1; cvt.u32.u64 %0, t; }"
        : "=r"(a) : "l"(p));
    return a;
}

__global__ __launch_bounds__(T)
void gat_kernel(const float* __restrict__ ego,          // [B, F]
                const float* __restrict__ neigh,        // [B, N, F]
                const int*   __restrict__ mask,         // [B, N] int32
                const float* __restrict__ W_ego,        // [F, F]
                const float* __restrict__ b_ego,        // [F]
                const float* __restrict__ w_attn,       // [2F]
                const float* __restrict__ b_attn,       // [1]
                const float* __restrict__ W_out,        // [F, OUT]
                const float* __restrict__ b_out,        // [OUT]
                float* __restrict__ out)                // [B, OUT]
{
    __shared__ alignas(128) float s_n[Nn * Fn];   // 16 KB neighbor row
    __shared__ alignas(128) int   s_m[Nn];        // 2 KB mask row
    __shared__ alignas(8) uint64_t mbar;
    __shared__ float s_max[4], s_sum[4], s_part[4][Fn], s_tb, s_agg[Fn];

    const int b    = blockIdx.x;
    const int t    = threadIdx.x;
    const int warp = t >> 5;
    const int lane = t & 31;

    // ---- Async bulk copy: zero register cost, full row in flight immediately.
    if (t == 0) {
        asm volatile("mbarrier.init.shared.b64 [%0], 1;"
                     :: "r"(s2u(&mbar)) : "memory");
    }
    __syncthreads();
    if (t == 0) {
        const uint32_t mb = s2u(&mbar);
        asm volatile("mbarrier.arrive.expect_tx.shared.b64 _, [%0], %1;"
                     :: "r"(mb), "r"(NEIGH_BYTES + MASK_BYTES) : "memory");
        asm volatile("cp.async.bulk.shared::cta.global.mbarrier::complete_tx::bytes "
                     "[%0], [%1], %2, [%3];"
                     :: "r"(s2u(s_n)), "l"(neigh + (size_t)b * (Nn * Fn)),
                        "r"(NEIGH_BYTES), "r"(mb) : "memory");
        asm volatile("cp.async.bulk.shared::cta.global.mbarrier::complete_tx::bytes "
                     "[%0], [%1], %2, [%3];"
                     :: "r"(s2u(s_m)), "l"(mask + (size_t)b * Nn),
                        "r"(MASK_BYTES), "r"(mb) : "memory");

        // ---- Ego scalar overlapped with the copy (operands L1/L2-resident).
        float tb = b_attn[0];
#pragma unroll
        for (int j = 0; j < Fn; j++) {
            float p = b_ego[j];
#pragma unroll
            for (int i = 0; i < Fn; i++)
                p += ego[(size_t)b * Fn + i] * W_ego[i * Fn + j];
            tb += p * w_attn[j];
        }
        s_tb = tb;
    }

    // ---- Wait for data (acquire orders the async-proxy smem writes).
    {
        const uint32_t mb = s2u(&mbar);
        uint32_t done;
        asm volatile(
            "{\n\t.reg .pred p;\n\t"
            "mbarrier.try_wait.parity.acquire.cta.shared::cta.b64 p, [%1], 0;\n\t"
            "selp.b32 %0, 1, 0, p;\n\t}"
            : "=r"(done) : "r"(mb) : "memory");
        if (!done) {
            asm volatile(
                "{\n\t.reg .pred P1;\n\t"
                "W_%=:\n\t"
                "mbarrier.try_wait.parity.acquire.cta.shared::cta.b64 P1, [%0], 0, 0x989680;\n\t"
                "@P1 bra.uni D_%=;\n\t"
                "bra.uni W_%=;\n\t"
                "D_%=:\n\t}"
                :: "r"(mb) : "memory");
        }
    }
    __syncthreads();   // orders s_tb; all threads past the wait
    const float tb = s_tb;

    const float w0 = w_attn[Fn + 0], w1 = w_attn[Fn + 1];
    const float w2 = w_attn[Fn + 2], w3 = w_attn[Fn + 3];
    const float w4 = w_attn[Fn + 4], w5 = w_attn[Fn + 5];
    const float w6 = w_attn[Fn + 6], w7 = w_attn[Fn + 7];

    const float4* sn4 = reinterpret_cast<const float4*>(s_n);

    // ---- Pass 1: scores + masked max (values NOT held across passes -> low regs).
    constexpr float NEG = -1e9f;
    float sc[K];
    int   mk[K];
    float mx = NEG;
#pragma unroll
    for (int k = 0; k < K; k++) {
        const int r = t + k * T;
        const float4 a = sn4[2 * r];
        const float4 c = sn4[2 * r + 1];
        mk[k] = s_m[r];
        float s = tb + a.x * w0 + a.y * w1 + a.z * w2 + a.w * w3
                     + c.x * w4 + c.y * w5 + c.z * w6 + c.w * w7;
        sc[k] = mk[k] ? s : NEG;
        mx = fmaxf(mx, sc[k]);
    }
#pragma unroll
    for (int o = 16; o; o >>= 1)
        mx = fmaxf(mx, __shfl_xor_sync(0xffffffffu, mx, o));
    if (lane == 0) s_max[warp] = mx;
    __syncthreads();
    mx = fmaxf(fmaxf(s_max[0], s_max[1]), fmaxf(s_max[2], s_max[3]));

    // ---- exp + block sum (masked -> exact 0, matching reference semantics).
    float e[K];
    float sum = 0.f;
#pragma unroll
    for (int k = 0; k < K; k++) {
        e[k] = mk[k] ? __expf(sc[k] - mx) : 0.f;
        sum += e[k];
    }
#pragma unroll
    for (int o = 16; o; o >>= 1)
        sum += __shfl_xor_sync(0xffffffffu, sum, o);
    if (lane == 0) s_sum[warp] = sum;

    // ---- Pass 2: weighted aggregation, re-reading smem (cheap: LDS).
    float acc[Fn];
#pragma unroll
    for (int f = 0; f < Fn; f++) acc[f] = 0.f;
#pragma unroll
    for (int k = 0; k < K; k++) {
        const int r = t + k * T;
        const float4 a = sn4[2 * r];
        const float4 c = sn4[2 * r + 1];
        const float ek = e[k];
        acc[0] += ek * a.x;  acc[1] += ek * a.y;
        acc[2] += ek * a.z;  acc[3] += ek * a.w;
        acc[4] += ek * c.x;  acc[5] += ek * c.y;
        acc[6] += ek * c.z;  acc[7] += ek * c.w;
    }
#pragma unroll
    for (int o = 16; o; o >>= 1) {
#pragma unroll
        for (int f = 0; f < Fn; f++)
            acc[f] += __shfl_xor_sync(0xffffffffu, acc[f], o);
    }
    if (lane == 0) {
#pragma unroll
        for (int f = 0; f < Fn; f++) s_part[warp][f] = acc[f];
    }
    __syncthreads();

    // ---- Normalize (all-masked row: tot==0 -> agg=0 -> out=b_out).
    const float tot  = s_sum[0] + s_sum[1] + s_sum[2] + s_sum[3];
    const float rinv = (tot > 0.f) ? (1.f / tot) : 0.f;
    if (t < Fn)
        s_agg[t] = (s_part[0][t] + s_part[1][t] + s_part[2][t] + s_part[3][t]) * rinv;
    __syncthreads();

    // ---- Output GEMV.
    if (t < On) {
        float v = b_out[t];
#pragma unroll
        for (int f = 0; f < Fn; f++)
            v += s_agg[f] * W_out[f * On + t];
        out[(size_t)b * On + t] = v;
    }
}

} // namespace

extern "C" void kernel_launch(void* const* d_in, const int* in_sizes, int n_in,
                              void* d_out, int out_size)
{
    const float* ego    = (const float*)d_in[0];
    const float* neigh  = (const float*)d_in[1];
    const int*   mask   = (const int*)d_in[2];
    const float* W_ego  = (const float*)d_in[3];
    const float* b_ego  = (const float*)d_in[4];
    const float* w_attn = (const float*)d_in[5];
    const float* b_attn = (const float*)d_in[6];
    const float* W_out  = (const float*)d_in[7];
    const float* b_out  = (const float*)d_in[8];
    float*       out    = (float*)d_out;

    gat_kernel<<<Bn, T>>>(ego, neigh, mask, W_ego, b_ego, w_attn, b_attn,
                          W_out, b_out, out);
}

// round 7
// speedup vs baseline: 2.1346x; 1.1330x over previous
#include <cuda_runtime.h>
#include <cstdint>

namespace {

constexpr int Bn = 32768;
constexpr int Nn = 512;
constexpr int Fn = 8;
constexpr int On = 32;
constexpr int T  = 128;
constexpr int NBLK = 912;                      // 152 SMs x 6 resident blocks

constexpr unsigned NEIGH_BYTES = Nn * Fn * 4;  // 16384
constexpr unsigned MASK_BYTES  = Nn * 4;       // 2048

__device__ __forceinline__ uint32_t s2u(const void* p) {
    uint32_t a;
    asm("{ .reg .u64 t; cvta.to.shared.u64 t, %1; cvt.u32.u64 %0, t; }"
        : "=r"(a) : "l"(p));
    return a;
}

__device__ __forceinline__ void wait_parity(uint32_t mb, uint32_t ph) {
    uint32_t done;
    asm volatile(
        "{\n\t.reg .pred p;\n\t"
        "mbarrier.try_wait.parity.acquire.cta.shared::cta.b64 p, [%1], %2;\n\t"
        "selp.b32 %0, 1, 0, p;\n\t}"
        : "=r"(done) : "r"(mb), "r"(ph) : "memory");
    if (!done) {
        asm volatile(
            "{\n\t.reg .pred P1;\n\t"
            "W_%=:\n\t"
            "mbarrier.try_wait.parity.acquire.cta.shared::cta.b64 P1, [%0], %1, 0x989680;\n\t"
            "@P1 bra.uni D_%=;\n\t"
            "bra.uni W_%=;\n\t"
            "D_%=:\n\t}"
            :: "r"(mb), "r"(ph) : "memory");
    }
}

__global__ __launch_bounds__(T)
void gat_kernel(const float* __restrict__ ego,          // [B, F]
                const float* __restrict__ neigh,        // [B, N, F]
                const int*   __restrict__ mask,         // [B, N] int32
                const float* __restrict__ W_ego,        // [F, F]
                const float* __restrict__ b_ego,        // [F]
                const float* __restrict__ w_attn,       // [2F]
                const float* __restrict__ b_attn,       // [1]
                const float* __restrict__ W_out,        // [F, OUT]
                const float* __restrict__ b_out,        // [OUT]
                float* __restrict__ out)                // [B, OUT]
{
    __shared__ alignas(128) float s_n[2][Nn * Fn];      // 2 x 16 KB
    __shared__ alignas(128) int   s_m[2][Nn];           // 2 x 2 KB
    __shared__ alignas(8) uint64_t mbar[2];
    __shared__ float s_max[4], s_sum[4], s_part[4][Fn], s_tb, s_agg[Fn];

    const int t    = threadIdx.x;
    const int warp = t >> 5;
    const int lane = t & 31;
    const int b0   = blockIdx.x;
    const int nrows = (Bn - b0 + NBLK - 1) / NBLK;

    if (t == 0) {
        asm volatile("mbarrier.init.shared.b64 [%0], 1;" :: "r"(s2u(&mbar[0])) : "memory");
        asm volatile("mbarrier.init.shared.b64 [%0], 1;" :: "r"(s2u(&mbar[1])) : "memory");
    }
    __syncthreads();

    // ---- TMA issue for local row i (t==0 only).
    auto issue = [&](int i) {
        const size_t b = (size_t)b0 + (size_t)i * NBLK;
        const int s = i & 1;
        const uint32_t mb = s2u(&mbar[s]);
        asm volatile("mbarrier.arrive.expect_tx.shared.b64 _, [%0], %1;"
                     :: "r"(mb), "r"(NEIGH_BYTES + MASK_BYTES) : "memory");
        asm volatile("cp.async.bulk.shared::cta.global.mbarrier::complete_tx::bytes "
                     "[%0], [%1], %2, [%3];"
                     :: "r"(s2u(s_n[s])), "l"(neigh + b * (Nn * Fn)),
                        "r"(NEIGH_BYTES), "r"(mb) : "memory");
        asm volatile("cp.async.bulk.shared::cta.global.mbarrier::complete_tx::bytes "
                     "[%0], [%1], %2, [%3];"
                     :: "r"(s2u(s_m[s])), "l"(mask + b * Nn),
                        "r"(MASK_BYTES), "r"(mb) : "memory");
    };

    if (t == 0) {
        if (nrows > 0) issue(0);
        if (nrows > 1) issue(1);
    }

    // wa_n in registers; half-row weight selection is constant per thread (t&1).
    const int half = t & 1;
    const float wa = w_attn[Fn + half * 4 + 0];
    const float wb = w_attn[Fn + half * 4 + 1];
    const float wc = w_attn[Fn + half * 4 + 2];
    const float wd = w_attn[Fn + half * 4 + 3];

    for (int i = 0; i < nrows; i++) {
        const size_t b = (size_t)b0 + (size_t)i * NBLK;
        const int s = i & 1;
        const uint32_t ph = (i >> 1) & 1;

        // ---- Ego scalar for this row (overlapped with TMA wait).
        if (t == 0) {
            float tb = b_attn[0];
#pragma unroll
            for (int j = 0; j < Fn; j++) {
                float p = b_ego[j];
#pragma unroll
                for (int k = 0; k < Fn; k++)
                    p += ego[b * Fn + k] * W_ego[k * Fn + j];
                tb += p * w_attn[j];
            }
            s_tb = tb;
        }

        wait_parity(s2u(&mbar[s]), ph);
        __syncthreads();                 // data visible to all; s_tb ordered
        const float tb = s_tb;

        const float4* sn4 = reinterpret_cast<const float4*>(s_n[s]);
        constexpr float NEG = -1e9f;

        // ---- Pass 1: half-row scores. Lane stride 16B -> conflict-free LDS.128.
        // Thread t handles half #(t&1) of rows r = (t>>1) + j*64.
        float sc[8];
        float mx = NEG;
#pragma unroll
        for (int j = 0; j < 8; j++) {
            const int q = t + j * T;         // half-row index
            const int r = (t >> 1) + j * 64; // row index
            const float4 v = sn4[q];
            float p = v.x * wa + v.y * wb + v.z * wc + v.w * wd;
            p += __shfl_xor_sync(0xffffffffu, p, 1);   // combine halves
            float scj = tb + p;
            scj = s_m[s][r] ? scj : NEG;
            sc[j] = scj;
            mx = fmaxf(mx, scj);
        }
#pragma unroll
        for (int o = 16; o; o >>= 1)
            mx = fmaxf(mx, __shfl_xor_sync(0xffffffffu, mx, o));
        if (lane == 0) s_max[warp] = mx;
        __syncthreads();
        mx = fmaxf(fmaxf(s_max[0], s_max[1]), fmaxf(s_max[2], s_max[3]));

        // ---- exp + sum (each row counted once: even lanes only).
        float e[8];
        float sum = 0.f;
#pragma unroll
        for (int j = 0; j < 8; j++) {
            e[j] = (sc[j] > -5e8f) ? __expf(sc[j] - mx) : 0.f;
            if (half == 0) sum += e[j];
        }
#pragma unroll
        for (int o = 16; o; o >>= 1)
            sum += __shfl_xor_sync(0xffffffffu, sum, o);
        if (lane == 0) s_sum[warp] = sum;

        // ---- Pass 2: weighted aggregation over my 4 features.
        float a0 = 0.f, a1 = 0.f, a2 = 0.f, a3 = 0.f;
#pragma unroll
        for (int j = 0; j < 8; j++) {
            const float4 v = sn4[t + j * T];
            const float ek = e[j];
            a0 += ek * v.x; a1 += ek * v.y; a2 += ek * v.z; a3 += ek * v.w;
        }
        __syncthreads();                 // all smem reads of stage s complete
        if (t == 0 && i + 2 < nrows) issue(i + 2);   // keep DRAM streaming

        // Parity-preserving butterfly: even lanes reduce feats 0-3, odd 4-7.
#pragma unroll
        for (int o = 16; o >= 2; o >>= 1) {
            a0 += __shfl_xor_sync(0xffffffffu, a0, o);
            a1 += __shfl_xor_sync(0xffffffffu, a1, o);
            a2 += __shfl_xor_sync(0xffffffffu, a2, o);
            a3 += __shfl_xor_sync(0xffffffffu, a3, o);
        }
        if (lane < 2) {
            s_part[warp][half * 4 + 0] = a0;
            s_part[warp][half * 4 + 1] = a1;
            s_part[warp][half * 4 + 2] = a2;
            s_part[warp][half * 4 + 3] = a3;
        }
        __syncthreads();

        // ---- Normalize (all-masked: tot==0 -> agg=0 -> out=b_out).
        if (t < Fn) {
            const float tot = s_sum[0] + s_sum[1] + s_sum[2] + s_sum[3];
            const float rinv = (tot > 0.f) ? (1.f / tot) : 0.f;
            s_agg[t] = (s_part[0][t] + s_part[1][t] + s_part[2][t] + s_part[3][t]) * rinv;
        }
        __syncthreads();

        // ---- Output GEMV.
        if (t < On) {
            float v = b_out[t];
#pragma unroll
            for (int f = 0; f < Fn; f++)
                v += s_agg[f] * W_out[f * On + t];
            out[b * On + t] = v;
        }
        // next iteration's wait + sync orders reuse of s_agg/s_part/s_tb
    }
}

} // namespace

extern "C" void kernel_launch(void* const* d_in, const int* in_sizes, int n_in,
                              void* d_out, int out_size)
{
    const float* ego    = (const float*)d_in[0];
    const float* neigh  = (const float*)d_in[1];
    const int*   mask   = (const int*)d_in[2];
    const float* W_ego  = (const float*)d_in[3];
    const float* b_ego  = (const float*)d_in[4];
    const float* w_attn = (const float*)d_in[5];
    const float* b_attn = (const float*)d_in[6];
    const float* W_out  = (const float*)d_in[7];
    const float* b_out  = (const float*)d_in[8];
    float*       out    = (float*)d_out;

    gat_kernel<<<NBLK, T>>>(ego, neigh, mask, W_ego, b_ego, w_attn, b_attn,
                            W_out, b_out, out);
}